// round 4
// baseline (speedup 1.0000x reference)
#include <cuda_runtime.h>
#include <cuda_bf16.h>
#include <cstdint>

// Problem constants (shapes fixed by setup_inputs)
#define HW      (1024 * 1024)             // pixels per channel
#define NBINS   16
#define NTOT    (NBINS * NBINS * NBINS)   // 4096
#define NPAIR   (NTOT / 2)                // 2048 paired (64-bit) bins
#define NIMG    9                         // 8 input images + 1 style image
#define BPI     64                        // blocks per image
#define TPB     512                       // threads per block (16 warps)
#define NCTA    (BPI * NIMG)              // 576 CTAs total

// Global scratch (zero-initialized at module load; last CTA re-zeros each run).
// Each 64-bit word packs two adjacent 32-bit bin counts.
__device__ unsigned long long g_hist2[NIMG][NPAIR];
__device__ unsigned int       g_done;

// searchsorted(boundaries, v, side='left') with boundaries = i/8 - 1, i=1..15.
// = count of boundaries strictly < v = clamp(ceil(8*(v+1)) - 1, 0, 15).
__device__ __forceinline__ int bin_of(float v) {
    int i = __float2int_ru(fmaf(v, 8.0f, 8.0f)) - 1;   // single F2I.CEIL
    i = max(i, 0);
    i = min(i, 15);
    return i;
}

__device__ __forceinline__ int flat_bin(float r, float g, float b) {
    return bin_of(r) + (bin_of(g) << 4) + (bin_of(b) << 8);
}

// ---------------------------------------------------------------------------
// Single fused kernel: histogram + global flush + last-CTA loss + state reset.
// grid = (BPI, NIMG), block = TPB.
// ---------------------------------------------------------------------------
__global__ __launch_bounds__(TPB) void fused_colorloss_kernel(
    const float* __restrict__ inp,   // [8, 3, H, W]
    const float* __restrict__ sty,   // [1, 3, H, W]
    float* __restrict__ out)         // [1]
{
    __shared__ int sh[NTOT];         // 16 KB per-CTA histogram
    #pragma unroll
    for (int i = threadIdx.x; i < NTOT; i += TPB) sh[i] = 0;
    __syncthreads();

    const int img = blockIdx.y;
    const float* base = (img < 8) ? (inp + (size_t)img * 3 * HW) : sty;

    const float4* r4 = (const float4*)(base);
    const float4* g4 = (const float4*)(base + HW);
    const float4* b4 = (const float4*)(base + 2 * HW);

    const int per_block = (HW / 4) / BPI;          // 4096 float4 per channel
    const int start     = blockIdx.x * per_block;
    const int end       = start + per_block;

    #pragma unroll 2
    for (int i = start + threadIdx.x; i < end; i += TPB) {
        float4 r = __ldcs(&r4[i]);
        float4 g = __ldcs(&g4[i]);
        float4 b = __ldcs(&b4[i]);

        int f0 = flat_bin(r.x, g.x, b.x);
        int f1 = flat_bin(r.y, g.y, b.y);
        int f2 = flat_bin(r.z, g.z, b.z);
        int f3 = flat_bin(r.w, g.w, b.w);

        atomicAdd(&sh[f0], 1);
        atomicAdd(&sh[f1], 1);
        atomicAdd(&sh[f2], 1);
        atomicAdd(&sh[f3], 1);
    }
    __syncthreads();

    // Flush: pack two adjacent bins into one 64-bit atomic (counts < 2^32).
    #pragma unroll
    for (int i = threadIdx.x; i < NPAIR; i += TPB) {
        unsigned int lo = (unsigned int)sh[2 * i];
        unsigned int hi = (unsigned int)sh[2 * i + 1];
        if (lo | hi) {
            atomicAdd(&g_hist2[img][i],
                      (unsigned long long)lo | ((unsigned long long)hi << 32));
        }
    }

    // --- last-CTA detection (threadfence-reduction pattern) ---
    __threadfence();
    __syncthreads();
    __shared__ int is_last;
    if (threadIdx.x == 0) {
        unsigned int ticket = atomicAdd(&g_done, 1u);
        is_last = (ticket == (unsigned int)(NCTA - 1));
    }
    __syncthreads();
    if (!is_last) return;

    // --- last CTA: exact integer L1 loss ---
    // Reuse sh[] to cache the unpacked style histogram.
    #pragma unroll
    for (int i = threadIdx.x; i < NPAIR; i += TPB) {
        unsigned long long p = __ldcg(&g_hist2[8][i]);
        sh[2 * i]     = (int)(unsigned int)(p & 0xffffffffULL);
        sh[2 * i + 1] = (int)(unsigned int)(p >> 32);
    }
    __syncthreads();

    int acc = 0;   // max possible sum = 2*8*HW = 16.8M < 2^31
    #pragma unroll 1
    for (int b = 0; b < 8; b++) {
        for (int i = threadIdx.x; i < NPAIR; i += TPB) {
            unsigned long long p = __ldcg(&g_hist2[b][i]);
            int d0 = (int)(unsigned int)(p & 0xffffffffULL) - sh[2 * i];
            int d1 = (int)(unsigned int)(p >> 32)           - sh[2 * i + 1];
            acc += (d0 < 0 ? -d0 : d0) + (d1 < 0 ? -d1 : d1);
        }
    }

    // block reduction
    #pragma unroll
    for (int o = 16; o > 0; o >>= 1)
        acc += __shfl_xor_sync(0xffffffffu, acc, o);

    __shared__ int warp_sum[TPB / 32];
    if ((threadIdx.x & 31) == 0) warp_sum[threadIdx.x >> 5] = acc;
    __syncthreads();

    if (threadIdx.x == 0) {
        long long total = 0;
        #pragma unroll
        for (int w = 0; w < TPB / 32; w++) total += warp_sum[w];
        out[0] = (float)((double)total /
                         ((double)HW * 8.0 * (double)NTOT));
    }

    // --- reset scratch for the next graph replay ---
    __syncthreads();
    unsigned long long* flat = (unsigned long long*)g_hist2;
    #pragma unroll
    for (int i = threadIdx.x; i < NIMG * NPAIR; i += TPB) flat[i] = 0ULL;
    if (threadIdx.x == 0) g_done = 0u;
}

// ---------------------------------------------------------------------------
// Launch contract
// ---------------------------------------------------------------------------
extern "C" void kernel_launch(void* const* d_in, const int* in_sizes, int n_in,
                              void* d_out, int out_size)
{
    const float* inp = (const float*)d_in[0];   // [8,3,1024,1024] fp32
    const float* sty = (const float*)d_in[1];   // [1,3,1024,1024] fp32
    float* out = (float*)d_out;

    dim3 grid(BPI, NIMG);
    fused_colorloss_kernel<<<grid, TPB>>>(inp, sty, out);
}

// round 6
// speedup vs baseline: 1.1222x; 1.1222x over previous
#include <cuda_runtime.h>
#include <cuda_bf16.h>
#include <cstdint>

// Problem constants (shapes fixed by setup_inputs)
#define HW      (1024 * 1024)             // pixels per channel
#define NBINS   16
#define NTOT    (NBINS * NBINS * NBINS)   // 4096
#define NPAIR   (NTOT / 2)                // 2048 paired (64-bit) bins
#define NIMG    9                         // 8 input images + 1 style image
#define BPI     128                       // blocks per image
#define TPB     256                       // threads per block
#define NCTA    (BPI * NIMG)              // 1152 CTAs

// Global scratch (zero-initialized at module load; loss kernel re-zeros it
// after each use, so every graph replay sees clean state).
__device__ unsigned long long g_hist2[NIMG][NPAIR];

// Skewed shared-memory layout: rotate the low-5-bit lane (bank) by the row
// index so that the Gaussian-hot corner bins spread across banks instead of
// piling onto banks {0,15,16,31}. Bijective within each 32-entry row.
__device__ __forceinline__ int skew(int f) {
    return (f & ~31) | ((f + (f >> 5)) & 31);
}
__device__ __forceinline__ int unskew(int s) {
    return (s & ~31) | ((s - (s >> 5)) & 31);
}

// searchsorted(boundaries, v, side='left') with boundaries = i/8 - 1, i=1..15.
// = count of boundaries strictly < v = clamp(ceil(8*(v+1)) - 1, 0, 15).
__device__ __forceinline__ int bin_of(float v) {
    int i = __float2int_ru(fmaf(v, 8.0f, 8.0f)) - 1;   // single F2I.CEIL
    i = max(i, 0);
    i = min(i, 15);
    return i;
}

__device__ __forceinline__ int flat_bin(float r, float g, float b) {
    return bin_of(r) + (bin_of(g) << 4) + (bin_of(b) << 8);
}

// ---------------------------------------------------------------------------
// Kernel A: per-image histogram. grid = (BPI, NIMG), block = TPB.
// Per-CTA 4096-bin shared histogram (skewed layout), 64-bit packed flush.
// ---------------------------------------------------------------------------
__global__ __launch_bounds__(TPB) void hist_kernel(
    const float* __restrict__ inp,   // [8, 3, H, W]
    const float* __restrict__ sty)   // [1, 3, H, W]
{
    __shared__ int sh[NTOT];         // 16 KB per-CTA histogram (skewed)
    #pragma unroll
    for (int i = threadIdx.x; i < NTOT; i += TPB) sh[i] = 0;
    __syncthreads();

    const int img = blockIdx.y;
    const float* base = (img < 8) ? (inp + (size_t)img * 3 * HW) : sty;

    const float4* r4 = (const float4*)(base);
    const float4* g4 = (const float4*)(base + HW);
    const float4* b4 = (const float4*)(base + 2 * HW);

    const int per_block = (HW / 4) / BPI;          // 2048 float4 per channel
    const int start     = blockIdx.x * per_block;
    const int end       = start + per_block;

    // 4 iterations of 2*TPB stride; 6 front-batched LDG.128 per iteration
    // for explicit MLP, then 8 shared atomics.
    for (int i = start + threadIdx.x; i < end; i += 2 * TPB) {
        float4 ra = r4[i];
        float4 rb = r4[i + TPB];
        float4 ga = g4[i];
        float4 gb = g4[i + TPB];
        float4 ba = b4[i];
        float4 bb = b4[i + TPB];

        atomicAdd(&sh[skew(flat_bin(ra.x, ga.x, ba.x))], 1);
        atomicAdd(&sh[skew(flat_bin(ra.y, ga.y, ba.y))], 1);
        atomicAdd(&sh[skew(flat_bin(ra.z, ga.z, ba.z))], 1);
        atomicAdd(&sh[skew(flat_bin(ra.w, ga.w, ba.w))], 1);
        atomicAdd(&sh[skew(flat_bin(rb.x, gb.x, bb.x))], 1);
        atomicAdd(&sh[skew(flat_bin(rb.y, gb.y, bb.y))], 1);
        atomicAdd(&sh[skew(flat_bin(rb.z, gb.z, bb.z))], 1);
        atomicAdd(&sh[skew(flat_bin(rb.w, gb.w, bb.w))], 1);
    }
    __syncthreads();

    // Flush: unskew, pack two adjacent f-bins into one 64-bit atomic.
    #pragma unroll
    for (int fp = threadIdx.x; fp < NPAIR; fp += TPB) {
        unsigned int lo = (unsigned int)sh[skew(2 * fp)];
        unsigned int hi = (unsigned int)sh[skew(2 * fp + 1)];
        if (lo | hi) {
            atomicAdd(&g_hist2[img][fp],
                      (unsigned long long)lo | ((unsigned long long)hi << 32));
        }
    }
}

// ---------------------------------------------------------------------------
// Kernel B: loss + scratch reset. One block of 1024 threads.
// loss = sum_{b,j} |h[b][j] - h[style][j]| / (HW * 8 * NTOT)   (exact ints)
// ---------------------------------------------------------------------------
__global__ __launch_bounds__(1024) void loss_kernel(float* __restrict__ out) {
    __shared__ int sh_sty[NTOT];

    // cache style histogram (unpacked)
    for (int i = threadIdx.x; i < NPAIR; i += 1024) {
        unsigned long long p = g_hist2[8][i];
        sh_sty[2 * i]     = (int)(unsigned int)(p & 0xffffffffULL);
        sh_sty[2 * i + 1] = (int)(unsigned int)(p >> 32);
    }
    __syncthreads();

    int acc = 0;   // max possible sum = 2*8*HW = 16.8M < 2^31
    #pragma unroll 1
    for (int b = 0; b < 8; b++) {
        for (int i = threadIdx.x; i < NPAIR; i += 1024) {
            unsigned long long p = g_hist2[b][i];
            int d0 = (int)(unsigned int)(p & 0xffffffffULL) - sh_sty[2 * i];
            int d1 = (int)(unsigned int)(p >> 32)           - sh_sty[2 * i + 1];
            acc += (d0 < 0 ? -d0 : d0) + (d1 < 0 ? -d1 : d1);
        }
    }

    // block reduction
    #pragma unroll
    for (int o = 16; o > 0; o >>= 1)
        acc += __shfl_xor_sync(0xffffffffu, acc, o);

    __shared__ int warp_sum[32];
    if ((threadIdx.x & 31) == 0) warp_sum[threadIdx.x >> 5] = acc;
    __syncthreads();

    if (threadIdx.x == 0) {
        long long total = 0;
        #pragma unroll
        for (int w = 0; w < 32; w++) total += warp_sum[w];
        out[0] = (float)((double)total /
                         ((double)HW * 8.0 * (double)NTOT));
    }

    // reset scratch for the next graph replay
    __syncthreads();
    unsigned long long* flat = (unsigned long long*)g_hist2;
    for (int i = threadIdx.x; i < NIMG * NPAIR; i += 1024) flat[i] = 0ULL;
}

// ---------------------------------------------------------------------------
// Launch contract
// ---------------------------------------------------------------------------
extern "C" void kernel_launch(void* const* d_in, const int* in_sizes, int n_in,
                              void* d_out, int out_size)
{
    const float* inp = (const float*)d_in[0];   // [8,3,1024,1024] fp32
    const float* sty = (const float*)d_in[1];   // [1,3,1024,1024] fp32
    float* out = (float*)d_out;

    dim3 grid(BPI, NIMG);
    hist_kernel<<<grid, TPB>>>(inp, sty);
    loss_kernel<<<1, 1024>>>(out);
}

// round 8
// speedup vs baseline: 1.3941x; 1.2423x over previous
#include <cuda_runtime.h>
#include <cuda_bf16.h>
#include <cstdint>

// Problem constants (shapes fixed by setup_inputs)
#define HW      (1024 * 1024)             // pixels per channel
#define NBINS   16
#define NTOT    (NBINS * NBINS * NBINS)   // 4096
#define NPAIR   (NTOT / 2)                // 2048 paired (64-bit) bins
#define NIMG    9                         // 8 input images + 1 style image
#define BPI     128                       // blocks per image
#define TPB     256                       // threads per block
#define NCTA    (BPI * NIMG)              // 1152 CTAs

#define LOSS_CTAS  16
#define LOSS_TPB   128                    // 16*128 = 2048 = NPAIR threads

// Global scratch (zero-initialized at module load; loss kernel re-zeros its
// own state after each use, so every graph replay sees clean state).
__device__ unsigned long long g_hist2[NIMG][NPAIR];
__device__ unsigned int       g_loss_acc;   // exact integer L1 sum
__device__ unsigned int       g_done;       // ticket for last-CTA detection

// Skewed shared-memory layout: rotate the low-5-bit lane (bank) by the row
// index so that the Gaussian-hot corner bins spread across banks instead of
// piling onto banks {0,15,16,31}. Bijective within each 32-entry row.
__device__ __forceinline__ int skew(int f) {
    return (f & ~31) | ((f + (f >> 5)) & 31);
}

// searchsorted(boundaries, v, side='left') with boundaries = i/8 - 1, i=1..15.
// = count of boundaries strictly < v = clamp(ceil(8*(v+1)) - 1, 0, 15).
__device__ __forceinline__ int bin_of(float v) {
    int i = __float2int_ru(fmaf(v, 8.0f, 8.0f)) - 1;   // single F2I.CEIL
    i = max(i, 0);
    i = min(i, 15);
    return i;
}

__device__ __forceinline__ int flat_bin(float r, float g, float b) {
    return bin_of(r) + (bin_of(g) << 4) + (bin_of(b) << 8);
}

// ---------------------------------------------------------------------------
// Kernel A: per-image histogram. grid = (BPI, NIMG), block = TPB.
// Per-CTA 4096-bin shared histogram (skewed layout), 64-bit packed flush.
// (At the HBM roofline — unchanged from round 6.)
// ---------------------------------------------------------------------------
__global__ __launch_bounds__(TPB) void hist_kernel(
    const float* __restrict__ inp,   // [8, 3, H, W]
    const float* __restrict__ sty)   // [1, 3, H, W]
{
    __shared__ int sh[NTOT];         // 16 KB per-CTA histogram (skewed)
    #pragma unroll
    for (int i = threadIdx.x; i < NTOT; i += TPB) sh[i] = 0;
    __syncthreads();

    const int img = blockIdx.y;
    const float* base = (img < 8) ? (inp + (size_t)img * 3 * HW) : sty;

    const float4* r4 = (const float4*)(base);
    const float4* g4 = (const float4*)(base + HW);
    const float4* b4 = (const float4*)(base + 2 * HW);

    const int per_block = (HW / 4) / BPI;          // 2048 float4 per channel
    const int start     = blockIdx.x * per_block;
    const int end       = start + per_block;

    // 6 front-batched LDG.128 per iteration for explicit MLP, then 8 atomics.
    for (int i = start + threadIdx.x; i < end; i += 2 * TPB) {
        float4 ra = r4[i];
        float4 rb = r4[i + TPB];
        float4 ga = g4[i];
        float4 gb = g4[i + TPB];
        float4 ba = b4[i];
        float4 bb = b4[i + TPB];

        atomicAdd(&sh[skew(flat_bin(ra.x, ga.x, ba.x))], 1);
        atomicAdd(&sh[skew(flat_bin(ra.y, ga.y, ba.y))], 1);
        atomicAdd(&sh[skew(flat_bin(ra.z, ga.z, ba.z))], 1);
        atomicAdd(&sh[skew(flat_bin(ra.w, ga.w, ba.w))], 1);
        atomicAdd(&sh[skew(flat_bin(rb.x, gb.x, bb.x))], 1);
        atomicAdd(&sh[skew(flat_bin(rb.y, gb.y, bb.y))], 1);
        atomicAdd(&sh[skew(flat_bin(rb.z, gb.z, bb.z))], 1);
        atomicAdd(&sh[skew(flat_bin(rb.w, gb.w, bb.w))], 1);
    }
    __syncthreads();

    // Flush: unskew, pack two adjacent f-bins into one 64-bit atomic.
    #pragma unroll
    for (int fp = threadIdx.x; fp < NPAIR; fp += TPB) {
        unsigned int lo = (unsigned int)sh[skew(2 * fp)];
        unsigned int hi = (unsigned int)sh[skew(2 * fp + 1)];
        if (lo | hi) {
            atomicAdd(&g_hist2[img][fp],
                      (unsigned long long)lo | ((unsigned long long)hi << 32));
        }
    }
}

// ---------------------------------------------------------------------------
// Kernel B: parallel loss + scratch reset. grid = LOSS_CTAS, block = LOSS_TPB.
// Each thread owns exactly one 64-bit pair index i and:
//   - loads style pair + 8 batch pairs (9 independent LDGs, full MLP)
//   - accumulates sum_b |h[b][i*] - h[8][i*]| (exact ints)
//   - resets its own 9 addresses (same-thread same-address, race-free)
// CTA partial sums land in g_loss_acc via one atomic; last CTA finalizes.
// ---------------------------------------------------------------------------
__global__ __launch_bounds__(LOSS_TPB) void loss_kernel(float* __restrict__ out)
{
    const int i = blockIdx.x * LOSS_TPB + threadIdx.x;   // pair index, < NPAIR

    // 9 independent loads (batched for MLP)
    unsigned long long ps = g_hist2[8][i];
    unsigned long long p0 = g_hist2[0][i];
    unsigned long long p1 = g_hist2[1][i];
    unsigned long long p2 = g_hist2[2][i];
    unsigned long long p3 = g_hist2[3][i];
    unsigned long long p4 = g_hist2[4][i];
    unsigned long long p5 = g_hist2[5][i];
    unsigned long long p6 = g_hist2[6][i];
    unsigned long long p7 = g_hist2[7][i];

    int slo = (int)(unsigned int)ps;
    int shi = (int)(unsigned int)(ps >> 32);

    int acc = 0;   // max 2*8*HW = 16.8M < 2^31
    #define ABS_DIFF(p) do {                                   \
        int d0 = (int)(unsigned int)(p) - slo;                 \
        int d1 = (int)(unsigned int)((p) >> 32) - shi;         \
        acc += (d0 < 0 ? -d0 : d0) + (d1 < 0 ? -d1 : d1);      \
    } while (0)
    ABS_DIFF(p0); ABS_DIFF(p1); ABS_DIFF(p2); ABS_DIFF(p3);
    ABS_DIFF(p4); ABS_DIFF(p5); ABS_DIFF(p6); ABS_DIFF(p7);
    #undef ABS_DIFF

    // reset this thread's slice of the scratch for the next graph replay
    #pragma unroll
    for (int b = 0; b < NIMG; b++) g_hist2[b][i] = 0ULL;

    // block reduction
    #pragma unroll
    for (int o = 16; o > 0; o >>= 1)
        acc += __shfl_xor_sync(0xffffffffu, acc, o);

    __shared__ int warp_sum[LOSS_TPB / 32];
    if ((threadIdx.x & 31) == 0) warp_sum[threadIdx.x >> 5] = acc;
    __syncthreads();

    __shared__ unsigned int my_ticket;
    if (threadIdx.x == 0) {
        int blk = 0;
        #pragma unroll
        for (int w = 0; w < LOSS_TPB / 32; w++) blk += warp_sum[w];
        atomicAdd(&g_loss_acc, (unsigned int)blk);
        __threadfence();
        my_ticket = atomicAdd(&g_done, 1u);
    }
    __syncthreads();

    if (threadIdx.x == 0 && my_ticket == (unsigned int)(LOSS_CTAS - 1)) {
        unsigned int total = atomicAdd(&g_loss_acc, 0u);   // coherent read
        out[0] = (float)((double)total /
                         ((double)HW * 8.0 * (double)NTOT));
        g_loss_acc = 0u;
        g_done = 0u;
    }
}

// ---------------------------------------------------------------------------
// Launch contract
// ---------------------------------------------------------------------------
extern "C" void kernel_launch(void* const* d_in, const int* in_sizes, int n_in,
                              void* d_out, int out_size)
{
    const float* inp = (const float*)d_in[0];   // [8,3,1024,1024] fp32
    const float* sty = (const float*)d_in[1];   // [1,3,1024,1024] fp32
    float* out = (float*)d_out;

    dim3 grid(BPI, NIMG);
    hist_kernel<<<grid, TPB>>>(inp, sty);
    loss_kernel<<<LOSS_CTAS, LOSS_TPB>>>(out);
}